// round 3
// baseline (speedup 1.0000x reference)
#include <cuda_runtime.h>
#include <cuda_bf16.h>
#include <math.h>

// Problem constants (fixed by the dataset; runtime values derived from in_sizes)
#define MAXN 100000
#define MAXE 1600000
#define HDIM 64

// ---------------- scratch (static device globals; no allocation) -------------
__device__ int   g_counts [MAXN];
__device__ int   g_offsets[MAXN];
__device__ int   g_cursor [MAXN];
__device__ float g_dis    [MAXN];
__device__ int   g_srcs   [MAXE];
__device__ float g_norms  [MAXE];
__device__ float g_agg    [MAXN * HDIM];
__device__ float g_h      [MAXN * HDIM];
__device__ int   g_bsum   [512];
__device__ int   g_is64;   // 1 if edge_index buffer is int64, 0 if int32

// ---------------- dtype probe -------------------------------------------------
// True int64 indices read as int64 lie in [0, n). An int32 buffer misread as
// int64 packs two indices per word -> values >= 2^32 (unless the odd index is
// exactly 0, vanishingly unlikely for all 8 samples). Deterministic.
__global__ void k_probe(const void* __restrict__ ei_raw, int n) {
    const long long* e64 = (const long long*)ei_raw;
    int ok64 = 1;
    for (int i = 0; i < 8; i++) {
        long long v = e64[i];
        if (v < 0 || v >= (long long)n) ok64 = 0;
    }
    g_is64 = ok64;
}

// ---------------- preprocessing: degree count + CSR build --------------------

__global__ void k_zero_counts(int n) {
    int i = blockIdx.x * blockDim.x + threadIdx.x;
    if (i < n) g_counts[i] = 0;
}

// edge_index is (2, E) row-major: [0..E) = src, [E..2E) = dst
__global__ void k_count(const void* __restrict__ ei_raw, int e, int n) {
    int i = blockIdx.x * blockDim.x + threadIdx.x;
    if (i < e) {
        int d;
        if (g_is64) d = (int)((const long long*)ei_raw)[(size_t)e + i];
        else        d = ((const int*)ei_raw)[(size_t)e + i];
        if ((unsigned)d < (unsigned)n) atomicAdd(&g_counts[d], 1);
    }
}

// Block-level exclusive scan of counts (512/block); also dis = rsqrt(deg+1)
__global__ void k_scan1(int n) {
    __shared__ int s[512];
    int t = threadIdx.x;
    int i = blockIdx.x * 512 + t;
    int v = (i < n) ? g_counts[i] : 0;
    s[t] = v;
    __syncthreads();
#pragma unroll
    for (int off = 1; off < 512; off <<= 1) {
        int tv = (t >= off) ? s[t - off] : 0;
        __syncthreads();
        s[t] += tv;
        __syncthreads();
    }
    if (i < n) {
        g_offsets[i] = s[t] - v;                  // exclusive within block
        g_dis[i]     = rsqrtf((float)(v + 1));    // deg includes self-loop
    }
    if (t == 511) g_bsum[blockIdx.x] = s[511];
}

// Exclusive scan of per-block sums (nb <= 512), single block
__global__ void k_scan2(int nb) {
    __shared__ int s[512];
    int t = threadIdx.x;
    int v = (t < nb) ? g_bsum[t] : 0;
    s[t] = v;
    __syncthreads();
#pragma unroll
    for (int off = 1; off < 512; off <<= 1) {
        int tv = (t >= off) ? s[t - off] : 0;
        __syncthreads();
        s[t] += tv;
        __syncthreads();
    }
    if (t < nb) g_bsum[t] = s[t] - v;             // exclusive
}

__global__ void k_scan3(int n) {
    int i = blockIdx.x * 512 + threadIdx.x;
    if (i < n) {
        int o = g_offsets[i] + g_bsum[blockIdx.x];
        g_offsets[i] = o;
        g_cursor[i]  = o;
    }
}

__global__ void k_fill(const void* __restrict__ ei_raw, int e, int n) {
    int i = blockIdx.x * blockDim.x + threadIdx.x;
    if (i < e) {
        int s, d;
        if (g_is64) {
            s = (int)((const long long*)ei_raw)[i];
            d = (int)((const long long*)ei_raw)[(size_t)e + i];
        } else {
            s = ((const int*)ei_raw)[i];
            d = ((const int*)ei_raw)[(size_t)e + i];
        }
        if ((unsigned)s < (unsigned)n && (unsigned)d < (unsigned)n) {
            int p = atomicAdd(&g_cursor[d], 1);
            g_srcs[p]  = s;
            g_norms[p] = g_dis[s] * g_dis[d];
        }
    }
}

// ---------------- aggregation: g_agg = A_norm_with_selfloops * in ------------
// Warp per destination node; lane handles feature columns lane and lane+32.
// in = xin (layer 1) or g_h (layers 2,3), selected by from_x.
__global__ void k_agg(const float* __restrict__ xin, int n, int from_x) {
    int warp = (blockIdx.x * blockDim.x + threadIdx.x) >> 5;
    int lane = threadIdx.x & 31;
    if (warp >= n) return;

    const float* __restrict__ in = from_x ? xin : (const float*)g_h;

    float di    = g_dis[warp];
    float selfc = di * di;

    const float* __restrict__ row = in + (size_t)warp * HDIM;
    float acc0 = __ldg(row + lane)      * selfc;
    float acc1 = __ldg(row + lane + 32) * selfc;

    int start = g_offsets[warp];
    int cnt   = g_counts[warp];
    for (int j = 0; j < cnt; j++) {
        int   s = g_srcs[start + j];    // broadcast load (all lanes same addr)
        float w = g_norms[start + j];
        const float* __restrict__ r2 = in + (size_t)s * HDIM;
        acc0 = fmaf(w, __ldg(r2 + lane),      acc0);
        acc1 = fmaf(w, __ldg(r2 + lane + 32), acc1);
    }
    g_agg[(size_t)warp * HDIM + lane]      = acc0;
    g_agg[(size_t)warp * HDIM + lane + 32] = acc1;
}

// ---------------- GEMM: out = [relu](g_agg @ W + b),  g_agg: n x 64 ----------
// 64-row tile per block, 256 threads, 4x4 register micro-tile.
// out = g_h (layers 1,2) or outp/d_out (layer 3), selected by to_out.
__global__ void k_gemm(const float* __restrict__ W, const float* __restrict__ b,
                       float* __restrict__ outp, int n, int do_relu, int to_out) {
    __shared__ float Ws[64 * 64];
    __shared__ float xs[64 * 68];   // transposed tile: xs[k*68 + r]; stride 68 keeps
                                    // float4 alignment and avoids bank conflicts
    const float* __restrict__ in  = (const float*)g_agg;
    float* __restrict__       out = to_out ? outp : (float*)g_h;

    int t = threadIdx.x;
    int row0 = blockIdx.x * 64;

    for (int i = t; i < 4096; i += 256) Ws[i] = W[i];
    for (int i = t; i < 4096; i += 256) {
        int r = i >> 6, k = i & 63;
        float v = (row0 + r < n) ? in[(size_t)(row0 + r) * HDIM + k] : 0.0f;
        xs[k * 68 + r] = v;
    }
    __syncthreads();

    int tx = t & 15, ty = t >> 4;   // col group (4 cols), row group (4 rows)
    int c0 = tx * 4, r0 = ty * 4;

    float acc[4][4] = {};
#pragma unroll
    for (int k = 0; k < 64; k++) {
        float4 xv = *(const float4*)&xs[k * 68 + r0];
        float4 wv = *(const float4*)&Ws[k * 64 + c0];
        acc[0][0] = fmaf(xv.x, wv.x, acc[0][0]);
        acc[0][1] = fmaf(xv.x, wv.y, acc[0][1]);
        acc[0][2] = fmaf(xv.x, wv.z, acc[0][2]);
        acc[0][3] = fmaf(xv.x, wv.w, acc[0][3]);
        acc[1][0] = fmaf(xv.y, wv.x, acc[1][0]);
        acc[1][1] = fmaf(xv.y, wv.y, acc[1][1]);
        acc[1][2] = fmaf(xv.y, wv.z, acc[1][2]);
        acc[1][3] = fmaf(xv.y, wv.w, acc[1][3]);
        acc[2][0] = fmaf(xv.z, wv.x, acc[2][0]);
        acc[2][1] = fmaf(xv.z, wv.y, acc[2][1]);
        acc[2][2] = fmaf(xv.z, wv.z, acc[2][2]);
        acc[2][3] = fmaf(xv.z, wv.w, acc[2][3]);
        acc[3][0] = fmaf(xv.w, wv.x, acc[3][0]);
        acc[3][1] = fmaf(xv.w, wv.y, acc[3][1]);
        acc[3][2] = fmaf(xv.w, wv.z, acc[3][2]);
        acc[3][3] = fmaf(xv.w, wv.w, acc[3][3]);
    }

    float4 bv = *(const float4*)&b[c0];
#pragma unroll
    for (int rr = 0; rr < 4; rr++) {
        int r = row0 + r0 + rr;
        if (r < n) {
            float4 o;
            o.x = acc[rr][0] + bv.x;
            o.y = acc[rr][1] + bv.y;
            o.z = acc[rr][2] + bv.z;
            o.w = acc[rr][3] + bv.w;
            if (do_relu) {
                o.x = fmaxf(o.x, 0.0f);
                o.y = fmaxf(o.y, 0.0f);
                o.z = fmaxf(o.z, 0.0f);
                o.w = fmaxf(o.w, 0.0f);
            }
            *(float4*)&out[(size_t)r * HDIM + c0] = o;
        }
    }
}

// ---------------- launch ------------------------------------------------------
extern "C" void kernel_launch(void* const* d_in, const int* in_sizes, int n_in,
                              void* d_out, int out_size) {
    const float* x  = (const float*)d_in[0];
    const void*  ei = d_in[1];
    // d_in[2] = edge_features (unused by GCNConv reference)
    const float* W1 = (const float*)d_in[3];
    const float* b1 = (const float*)d_in[4];
    const float* W2 = (const float*)d_in[5];
    const float* b2 = (const float*)d_in[6];
    const float* W3 = (const float*)d_in[7];
    const float* b3 = (const float*)d_in[8];
    float* outp = (float*)d_out;

    int N = in_sizes[0] / HDIM;
    int E = in_sizes[1] / 2;

    int nb = (N + 511) / 512;

    // ---- dtype probe + CSR build ----
    k_probe<<<1, 1>>>(ei, N);
    k_zero_counts<<<(N + 255) / 256, 256>>>(N);
    k_count<<<(E + 255) / 256, 256>>>(ei, E, N);
    k_scan1<<<nb, 512>>>(N);
    k_scan2<<<1, 512>>>(nb);
    k_scan3<<<nb, 512>>>(N);
    k_fill<<<(E + 255) / 256, 256>>>(ei, E, N);

    int agg_blocks  = (N * 32 + 255) / 256;
    int gemm_blocks = (N + 63) / 64;

    // ---- layer 1: agg(x) -> gemm(W1,b1)+relu -> g_h ----
    k_agg <<<agg_blocks, 256>>>(x, N, 1);
    k_gemm<<<gemm_blocks, 256>>>(W1, b1, outp, N, 1, 0);

    // ---- layer 2 ----
    k_agg <<<agg_blocks, 256>>>(x, N, 0);
    k_gemm<<<gemm_blocks, 256>>>(W2, b2, outp, N, 1, 0);

    // ---- layer 3 (no relu, direct to d_out) ----
    k_agg <<<agg_blocks, 256>>>(x, N, 0);
    k_gemm<<<gemm_blocks, 256>>>(W3, b3, outp, N, 0, 1);
}